// round 7
// baseline (speedup 1.0000x reference)
#include <cuda_runtime.h>

// Spread accumulator slots (zero-init at load; reset by last block each run).
#define NSLOT 32
__device__ double g_part0[NSLOT];          // class-0 picked log-prob partials
__device__ double g_part1[NSLOT];          // class-1 picked log-prob partials
__device__ unsigned long long g_pcnt[NSLOT];  // class-1 count partials
__device__ unsigned int g_blocks_done;     // retirement counter

__device__ __forceinline__ void proc_token(float x0, float x1, int t,
                                           float& s0, float& s1, int& c1) {
    // picked log-softmax value: x[t] - logsumexp(x0, x1)
    float m   = fmaxf(x0, x1);
    float d   = -fabsf(x0 - x1);
    float lse = m + __logf(1.0f + __expf(d));
    if (t != 0) {
        s1 += x1 - lse;
        c1 += 1;
    } else {
        s0 += x0 - lse;
    }
}

// R4-proven body: each thread owns 8 contiguous tokens, 6 front-batched
// 128-bit loads, no barrier before compute. 32 regs, 8 CTAs/SM.
__global__ __launch_bounds__(256, 8) void nll_fused_kernel(
    const float* __restrict__ x,
    const int* __restrict__ targets,
    long long n_tokens,
    float* __restrict__ out)
{
    const long long tid  = (long long)blockIdx.x * blockDim.x + threadIdx.x;
    const long long base = tid * 8;

    float s0 = 0.0f, s1 = 0.0f;
    int   c1 = 0;

    if (base + 7 < n_tokens) {
        const float4* x4 = reinterpret_cast<const float4*>(x) + base / 2;
        const int4*   t4 = reinterpret_cast<const int4*>(targets) + base / 4;
        float4 a0 = x4[0];
        float4 a1 = x4[1];
        float4 a2 = x4[2];
        float4 a3 = x4[3];
        int4   b0 = t4[0];
        int4   b1 = t4[1];

        proc_token(a0.x, a0.y, b0.x, s0, s1, c1);
        proc_token(a0.z, a0.w, b0.y, s0, s1, c1);
        proc_token(a1.x, a1.y, b0.z, s0, s1, c1);
        proc_token(a1.z, a1.w, b0.w, s0, s1, c1);
        proc_token(a2.x, a2.y, b1.x, s0, s1, c1);
        proc_token(a2.z, a2.w, b1.y, s0, s1, c1);
        proc_token(a3.x, a3.y, b1.z, s0, s1, c1);
        proc_token(a3.z, a3.w, b1.w, s0, s1, c1);
    } else {
        for (long long i = base; i < n_tokens && i < base + 8; i++) {
            proc_token(x[2 * i], x[2 * i + 1], targets[i], s0, s1, c1);
        }
    }

    // warp reduction
    #pragma unroll
    for (int off = 16; off > 0; off >>= 1) {
        s0 += __shfl_down_sync(0xFFFFFFFFu, s0, off);
        s1 += __shfl_down_sync(0xFFFFFFFFu, s1, off);
        c1 += __shfl_down_sync(0xFFFFFFFFu, c1, off);
    }

    __shared__ float sh0[8];
    __shared__ float sh1[8];
    __shared__ int   shc[8];
    const int lane = threadIdx.x & 31;
    const int wid  = threadIdx.x >> 5;
    if (lane == 0) { sh0[wid] = s0; sh1[wid] = s1; shc[wid] = c1; }
    __syncthreads();

    __shared__ bool is_last;
    if (wid == 0) {
        const int nw = blockDim.x >> 5;
        s0 = (lane < nw) ? sh0[lane] : 0.0f;
        s1 = (lane < nw) ? sh1[lane] : 0.0f;
        c1 = (lane < nw) ? shc[lane] : 0;
        #pragma unroll
        for (int off = 4; off > 0; off >>= 1) {
            s0 += __shfl_down_sync(0xFFFFFFFFu, s0, off);
            s1 += __shfl_down_sync(0xFFFFFFFFu, s1, off);
            c1 += __shfl_down_sync(0xFFFFFFFFu, c1, off);
        }
        if (lane == 0) {
            const int slot = blockIdx.x & (NSLOT - 1);
            atomicAdd(&g_part0[slot], (double)s0);
            atomicAdd(&g_part1[slot], (double)s1);
            atomicAdd(&g_pcnt[slot], (unsigned long long)c1);
            __threadfence();
            unsigned int done = atomicAdd(&g_blocks_done, 1u);
            is_last = (done == gridDim.x - 1u);
        }
    }
    __syncthreads();

    // Last block folds the 32 slots, writes output, resets state.
    if (is_last && threadIdx.x == 0) {
        __threadfence();
        double sum0 = 0.0, sum1 = 0.0;
        unsigned long long n1 = 0ull;
        #pragma unroll
        for (int s = 0; s < NSLOT; s++) {
            sum0 += g_part0[s];
            sum1 += g_part1[s];
            n1   += g_pcnt[s];
            g_part0[s] = 0.0;
            g_part1[s] = 0.0;
            g_pcnt[s]  = 0ull;
        }
        unsigned long long n0 = (unsigned long long)n_tokens - n1;
        double r = (n1 > 0) ? (-sum1 / (double)n1) : 0.0;
        double p = (n0 > 0) ? (-sum0 / (double)n0) : 0.0;
        out[0] = (float)(p + r);
        g_blocks_done = 0u;
    }
}

extern "C" void kernel_launch(void* const* d_in, const int* in_sizes, int n_in,
                              void* d_out, int out_size) {
    const float* x       = (const float*)d_in[0];
    const int*   targets = (const int*)d_in[1];
    float*       out     = (float*)d_out;

    const long long n_tokens = (long long)in_sizes[1];

    const long long threads_needed = (n_tokens + 7) / 8;
    const int block = 256;
    const int grid  = (int)((threads_needed + block - 1) / block);
    nll_fused_kernel<<<grid, block>>>(x, targets, n_tokens, out);
}

// round 8
// speedup vs baseline: 1.9142x; 1.9142x over previous
#include <cuda_runtime.h>
#include <cstdint>

// Global accumulators (zero-init at module load; last block resets each run).
__device__ double g_sum0;                  // class-0 picked log-prob sum
__device__ double g_sum1;                  // class-1 picked log-prob sum
__device__ unsigned long long g_cnt1;      // class-1 count
__device__ unsigned int g_blocks_done;     // retirement counter

#define TILE_PAIRS      1024     // pairs per tile (2048 tokens)
#define TILES_PER_BLOCK 4        // pairs per block = 4096
#define NSTAGE          2

__device__ __forceinline__ void cp_async16(void* smem_dst, const void* gmem_src) {
    uint32_t s = (uint32_t)__cvta_generic_to_shared(smem_dst);
    asm volatile("cp.async.cg.shared.global [%0], [%1], 16;" :: "r"(s), "l"(gmem_src));
}
__device__ __forceinline__ void cp_async_commit() {
    asm volatile("cp.async.commit_group;" ::: "memory");
}
template <int N>
__device__ __forceinline__ void cp_async_wait() {
    asm volatile("cp.async.wait_group %0;" :: "n"(N) : "memory");
}

__device__ __forceinline__ void proc_pair(float4 a, int2 t,
                                          float& s0, float& s1, int& c1) {
    {
        float m   = fmaxf(a.x, a.y);
        float d   = -fabsf(a.x - a.y);
        float lse = m + __logf(1.0f + __expf(d));
        if (t.x != 0) { s1 += a.y - lse; c1 += 1; }
        else          { s0 += a.x - lse; }
    }
    {
        float m   = fmaxf(a.z, a.w);
        float d   = -fabsf(a.z - a.w);
        float lse = m + __logf(1.0f + __expf(d));
        if (t.y != 0) { s1 += a.w - lse; c1 += 1; }
        else          { s0 += a.z - lse; }
    }
}

__global__ __launch_bounds__(256, 7) void nll_pipe_kernel(
    const float* __restrict__ x,
    const int* __restrict__ targets,
    long long n_tokens,
    float* __restrict__ out)
{
    __shared__ float4 xbuf[NSTAGE][TILE_PAIRS];   // 2 x 16 KB

    const int tix = threadIdx.x;
    const long long n_pairs = n_tokens >> 1;
    const long long P0 = (long long)blockIdx.x * (TILES_PER_BLOCK * TILE_PAIRS);

    const float4* x4 = reinterpret_cast<const float4*>(x);
    const int2*   t2 = reinterpret_cast<const int2*>(targets);

    float s0 = 0.0f, s1 = 0.0f;
    int   c1 = 0;

    const bool full_block = (P0 + TILES_PER_BLOCK * TILE_PAIRS) <= n_pairs;

    if (full_block) {
        // Prefetch first NSTAGE tiles.
        #pragma unroll
        for (int i = 0; i < NSTAGE; i++) {
            const float4* src = x4 + P0 + i * TILE_PAIRS + tix;
            #pragma unroll
            for (int k = 0; k < 4; k++)
                cp_async16(&xbuf[i][k * 256 + tix], src + k * 256);
            cp_async_commit();
        }

        #pragma unroll
        for (int i = 0; i < TILES_PER_BLOCK; i++) {
            const int st = i & (NSTAGE - 1);
            const long long tb = P0 + (long long)i * TILE_PAIRS;

            // Targets for this tile: 4 coalesced LDG.64, independent of smem —
            // issued before the pipeline wait so they overlap it.
            const int2* tp = t2 + tb + tix;
            int2 b0 = tp[0];
            int2 b1 = tp[256];
            int2 b2 = tp[512];
            int2 b3 = tp[768];

            cp_async_wait<NSTAGE - 1>();   // tile i's copy complete
            __syncthreads();

            float4 a0 = xbuf[st][tix];
            float4 a1 = xbuf[st][256 + tix];
            float4 a2 = xbuf[st][512 + tix];
            float4 a3 = xbuf[st][768 + tix];

            proc_pair(a0, b0, s0, s1, c1);
            proc_pair(a1, b1, s0, s1, c1);
            proc_pair(a2, b2, s0, s1, c1);
            proc_pair(a3, b3, s0, s1, c1);

            __syncthreads();               // everyone done reading buf st
            if (i + NSTAGE < TILES_PER_BLOCK) {
                const float4* src = x4 + P0 + (long long)(i + NSTAGE) * TILE_PAIRS + tix;
                #pragma unroll
                for (int k = 0; k < 4; k++)
                    cp_async16(&xbuf[st][k * 256 + tix], src + k * 256);
                cp_async_commit();
            }
        }
    } else {
        // Generic guarded path for the boundary block (rare / other shapes).
        for (long long p = P0 + tix; p < n_pairs &&
             p < P0 + TILES_PER_BLOCK * TILE_PAIRS; p += 256) {
            proc_pair(x4[p], t2[p], s0, s1, c1);
        }
    }

    // Odd trailing token.
    if ((n_tokens & 1) && blockIdx.x == 0 && tix == 0) {
        long long i = n_tokens - 1;
        float x0 = x[2 * i], x1v = x[2 * i + 1];
        int   t  = targets[i];
        float m   = fmaxf(x0, x1v);
        float d   = -fabsf(x0 - x1v);
        float lse = m + __logf(1.0f + __expf(d));
        if (t != 0) { s1 += x1v - lse; c1 += 1; }
        else        { s0 += x0 - lse; }
    }

    // warp reduction
    #pragma unroll
    for (int off = 16; off > 0; off >>= 1) {
        s0 += __shfl_down_sync(0xFFFFFFFFu, s0, off);
        s1 += __shfl_down_sync(0xFFFFFFFFu, s1, off);
        c1 += __shfl_down_sync(0xFFFFFFFFu, c1, off);
    }

    __shared__ float sh0[8];
    __shared__ float sh1[8];
    __shared__ int   shc[8];
    const int lane = tix & 31;
    const int wid  = tix >> 5;
    if (lane == 0) { sh0[wid] = s0; sh1[wid] = s1; shc[wid] = c1; }
    __syncthreads();

    __shared__ bool is_last;
    if (wid == 0) {
        s0 = (lane < 8) ? sh0[lane] : 0.0f;
        s1 = (lane < 8) ? sh1[lane] : 0.0f;
        c1 = (lane < 8) ? shc[lane] : 0;
        #pragma unroll
        for (int off = 4; off > 0; off >>= 1) {
            s0 += __shfl_down_sync(0xFFFFFFFFu, s0, off);
            s1 += __shfl_down_sync(0xFFFFFFFFu, s1, off);
            c1 += __shfl_down_sync(0xFFFFFFFFu, c1, off);
        }
        if (lane == 0) {
            atomicAdd(&g_sum0, (double)s0);
            atomicAdd(&g_sum1, (double)s1);
            atomicAdd(&g_cnt1, (unsigned long long)c1);
            __threadfence();
            unsigned int done = atomicAdd(&g_blocks_done, 1u);
            is_last = (done == gridDim.x - 1u);
        }
    }
    __syncthreads();

    if (is_last && tix == 0) {
        __threadfence();
        double sum0 = g_sum0;
        double sum1 = g_sum1;
        unsigned long long n1 = g_cnt1;
        unsigned long long n0 = (unsigned long long)n_tokens - n1;
        double r = (n1 > 0) ? (-sum1 / (double)n1) : 0.0;
        double p = (n0 > 0) ? (-sum0 / (double)n0) : 0.0;
        out[0] = (float)(p + r);
        g_sum0 = 0.0;
        g_sum1 = 0.0;
        g_cnt1 = 0ull;
        g_blocks_done = 0u;
    }
}

extern "C" void kernel_launch(void* const* d_in, const int* in_sizes, int n_in,
                              void* d_out, int out_size) {
    const float* x       = (const float*)d_in[0];
    const int*   targets = (const int*)d_in[1];
    float*       out     = (float*)d_out;

    const long long n_tokens = (long long)in_sizes[1];
    const long long n_pairs  = (n_tokens + 1) / 2;

    const int block = 256;
    const long long pairs_per_block = TILES_PER_BLOCK * TILE_PAIRS;  // 4096
    int grid = (int)((n_pairs + pairs_per_block - 1) / pairs_per_block);
    if (grid < 1) grid = 1;
    nll_pipe_kernel<<<grid, block>>>(x, targets, n_tokens, out);
}

// round 9
// speedup vs baseline: 1.9213x; 1.0037x over previous
#include <cuda_runtime.h>
#include <cstdint>

// Global accumulators (zero-init at module load; last block resets each run).
__device__ double g_sum0;                  // class-0 picked log-prob sum
__device__ double g_sum1;                  // class-1 picked log-prob sum
__device__ unsigned long long g_cnt1;      // class-1 count
__device__ unsigned int g_blocks_done;     // retirement counter

#define TILE_PAIRS      1024     // pairs per tile (2048 tokens)
#define TILES_PER_BLOCK 4        // pairs per block = 4096
#define NSTAGE          2

__device__ __forceinline__ void cp_async16(void* smem_dst, const void* gmem_src) {
    uint32_t s = (uint32_t)__cvta_generic_to_shared(smem_dst);
    asm volatile("cp.async.cg.shared.global [%0], [%1], 16;" :: "r"(s), "l"(gmem_src));
}
__device__ __forceinline__ void cp_async_commit() {
    asm volatile("cp.async.commit_group;" ::: "memory");
}
template <int N>
__device__ __forceinline__ void cp_async_wait() {
    asm volatile("cp.async.wait_group %0;" :: "n"(N) : "memory");
}

__device__ __forceinline__ void proc_pair(float4 a, int2 t,
                                          float& s0, float& s1, int& c1) {
    {
        float m   = fmaxf(a.x, a.y);
        float d   = -fabsf(a.x - a.y);
        float lse = m + __logf(1.0f + __expf(d));
        if (t.x != 0) { s1 += a.y - lse; c1 += 1; }
        else          { s0 += a.x - lse; }
    }
    {
        float m   = fmaxf(a.z, a.w);
        float d   = -fabsf(a.z - a.w);
        float lse = m + __logf(1.0f + __expf(d));
        if (t.y != 0) { s1 += a.w - lse; c1 += 1; }
        else          { s0 += a.z - lse; }
    }
}

// Barrier-free per-thread streaming pipeline: every thread cp.asyncs ONLY the
// smem words it alone reads (xbuf[st][k*256+tix]), so cp.async.wait_group
// gives full self-visibility and no __syncthreads is needed in the loop.
// Warps slip freely past each other -> no block-lockstep bubbles.
__global__ __launch_bounds__(256, 7) void nll_pipe_kernel(
    const float* __restrict__ x,
    const int* __restrict__ targets,
    long long n_tokens,
    float* __restrict__ out)
{
    __shared__ float4 xbuf[NSTAGE][TILE_PAIRS];   // 2 x 16 KB

    const int tix = threadIdx.x;
    const long long n_pairs = n_tokens >> 1;
    const long long P0 = (long long)blockIdx.x * (TILES_PER_BLOCK * TILE_PAIRS);

    const float4* x4 = reinterpret_cast<const float4*>(x);
    const int2*   t2 = reinterpret_cast<const int2*>(targets);

    float s0 = 0.0f, s1 = 0.0f;
    int   c1 = 0;

    const bool full_block = (P0 + TILES_PER_BLOCK * TILE_PAIRS) <= n_pairs;

    if (full_block) {
        // Prefetch first NSTAGE tiles (one commit group per tile).
        #pragma unroll
        for (int i = 0; i < NSTAGE; i++) {
            const float4* src = x4 + P0 + i * TILE_PAIRS + tix;
            #pragma unroll
            for (int k = 0; k < 4; k++)
                cp_async16(&xbuf[i][k * 256 + tix], src + k * 256);
            cp_async_commit();
        }

        #pragma unroll
        for (int i = 0; i < TILES_PER_BLOCK; i++) {
            const int st = i & (NSTAGE - 1);
            const long long tb = P0 + (long long)i * TILE_PAIRS;

            // Targets for this tile: 4 coalesced LDG.64, independent of smem —
            // they overlap the cp.async wait below.
            const int2* tp = t2 + tb + tix;
            int2 b0 = tp[0];
            int2 b1 = tp[256];
            int2 b2 = tp[512];
            int2 b3 = tp[768];

            cp_async_wait<NSTAGE - 1>();   // this thread's tile-i copy done

            // Drain smem slots into registers (frees buf st for reuse by THIS
            // thread; no other thread ever touches these addresses).
            float4 a0 = xbuf[st][tix];
            float4 a1 = xbuf[st][256 + tix];
            float4 a2 = xbuf[st][512 + tix];
            float4 a3 = xbuf[st][768 + tix];

            // Refill buf st for tile i+NSTAGE before computing, maximizing
            // copy/compute overlap.
            if (i + NSTAGE < TILES_PER_BLOCK) {
                const float4* src = x4 + P0 + (long long)(i + NSTAGE) * TILE_PAIRS + tix;
                #pragma unroll
                for (int k = 0; k < 4; k++)
                    cp_async16(&xbuf[st][k * 256 + tix], src + k * 256);
                cp_async_commit();
            }

            proc_pair(a0, b0, s0, s1, c1);
            proc_pair(a1, b1, s0, s1, c1);
            proc_pair(a2, b2, s0, s1, c1);
            proc_pair(a3, b3, s0, s1, c1);
        }
    } else {
        // Generic guarded path for the boundary block (rare / other shapes).
        for (long long p = P0 + tix; p < n_pairs &&
             p < P0 + TILES_PER_BLOCK * TILE_PAIRS; p += 256) {
            proc_pair(x4[p], t2[p], s0, s1, c1);
        }
    }

    // Odd trailing token.
    if ((n_tokens & 1) && blockIdx.x == 0 && tix == 0) {
        long long i = n_tokens - 1;
        float x0 = x[2 * i], x1v = x[2 * i + 1];
        int   t  = targets[i];
        float m   = fmaxf(x0, x1v);
        float d   = -fabsf(x0 - x1v);
        float lse = m + __logf(1.0f + __expf(d));
        if (t != 0) { s1 += x1v - lse; c1 += 1; }
        else        { s0 += x0 - lse; }
    }

    // warp reduction
    #pragma unroll
    for (int off = 16; off > 0; off >>= 1) {
        s0 += __shfl_down_sync(0xFFFFFFFFu, s0, off);
        s1 += __shfl_down_sync(0xFFFFFFFFu, s1, off);
        c1 += __shfl_down_sync(0xFFFFFFFFu, c1, off);
    }

    __shared__ float sh0[8];
    __shared__ float sh1[8];
    __shared__ int   shc[8];
    const int lane = tix & 31;
    const int wid  = tix >> 5;
    if (lane == 0) { sh0[wid] = s0; sh1[wid] = s1; shc[wid] = c1; }
    __syncthreads();

    __shared__ bool is_last;
    if (wid == 0) {
        s0 = (lane < 8) ? sh0[lane] : 0.0f;
        s1 = (lane < 8) ? sh1[lane] : 0.0f;
        c1 = (lane < 8) ? shc[lane] : 0;
        #pragma unroll
        for (int off = 4; off > 0; off >>= 1) {
            s0 += __shfl_down_sync(0xFFFFFFFFu, s0, off);
            s1 += __shfl_down_sync(0xFFFFFFFFu, s1, off);
            c1 += __shfl_down_sync(0xFFFFFFFFu, c1, off);
        }
        if (lane == 0) {
            atomicAdd(&g_sum0, (double)s0);
            atomicAdd(&g_sum1, (double)s1);
            atomicAdd(&g_cnt1, (unsigned long long)c1);
            __threadfence();
            unsigned int done = atomicAdd(&g_blocks_done, 1u);
            is_last = (done == gridDim.x - 1u);
        }
    }
    __syncthreads();

    if (is_last && tix == 0) {
        __threadfence();
        double sum0 = g_sum0;
        double sum1 = g_sum1;
        unsigned long long n1 = g_cnt1;
        unsigned long long n0 = (unsigned long long)n_tokens - n1;
        double r = (n1 > 0) ? (-sum1 / (double)n1) : 0.0;
        double p = (n0 > 0) ? (-sum0 / (double)n0) : 0.0;
        out[0] = (float)(p + r);
        g_sum0 = 0.0;
        g_sum1 = 0.0;
        g_cnt1 = 0ull;
        g_blocks_done = 0u;
    }
}

extern "C" void kernel_launch(void* const* d_in, const int* in_sizes, int n_in,
                              void* d_out, int out_size) {
    const float* x       = (const float*)d_in[0];
    const int*   targets = (const int*)d_in[1];
    float*       out     = (float*)d_out;

    const long long n_tokens = (long long)in_sizes[1];
    const long long n_pairs  = (n_tokens + 1) / 2;

    const int block = 256;
    const long long pairs_per_block = TILES_PER_BLOCK * TILE_PAIRS;  // 4096
    int grid = (int)((n_pairs + pairs_per_block - 1) / pairs_per_block);
    if (grid < 1) grid = 1;
    nll_pipe_kernel<<<grid, block>>>(x, targets, n_tokens, out);
}

// round 10
// speedup vs baseline: 1.9395x; 1.0095x over previous
#include <cuda_runtime.h>
#include <cstdint>

// Global accumulators (zero-init at module load; last block resets each run).
__device__ double g_sum0;                  // class-0 picked log-prob sum
__device__ double g_sum1;                  // class-1 picked log-prob sum
__device__ unsigned long long g_cnt1;      // class-1 count
__device__ unsigned int g_blocks_done;     // retirement counter

#define TILE_PAIRS      512      // pairs per tile (1024 tokens) -> 8 KB/stage
#define TILES_PER_BLOCK 8        // pairs per block = 4096 (grid stays 1024)
#define NSTAGE          3        // 24 KB smem total -> 8 CTAs/SM, single wave

__device__ __forceinline__ void cp_async16(void* smem_dst, const void* gmem_src) {
    uint32_t s = (uint32_t)__cvta_generic_to_shared(smem_dst);
    asm volatile("cp.async.cg.shared.global [%0], [%1], 16;" :: "r"(s), "l"(gmem_src));
}
__device__ __forceinline__ void cp_async_commit() {
    asm volatile("cp.async.commit_group;" ::: "memory");
}
template <int N>
__device__ __forceinline__ void cp_async_wait() {
    asm volatile("cp.async.wait_group %0;" :: "n"(N) : "memory");
}

__device__ __forceinline__ void proc_pair(float4 a, int2 t,
                                          float& s0, float& s1, int& c1) {
    {
        float m   = fmaxf(a.x, a.y);
        float d   = -fabsf(a.x - a.y);
        float lse = m + __logf(1.0f + __expf(d));
        if (t.x != 0) { s1 += a.y - lse; c1 += 1; }
        else          { s0 += a.x - lse; }
    }
    {
        float m   = fmaxf(a.z, a.w);
        float d   = -fabsf(a.z - a.w);
        float lse = m + __logf(1.0f + __expf(d));
        if (t.y != 0) { s1 += a.w - lse; c1 += 1; }
        else          { s0 += a.z - lse; }
    }
}

// Barrier-free per-thread streaming pipeline (proven in R8/R9): each thread
// cp.asyncs ONLY the smem words it alone reads, so cp.async.wait_group gives
// self-visibility and no __syncthreads is needed in the loop. This round:
// 3-stage x 8KB tiles => 24KB smem => 8 CTAs/SM => grid 1024 fits in ONE wave.
__global__ __launch_bounds__(256, 8) void nll_pipe_kernel(
    const float* __restrict__ x,
    const int* __restrict__ targets,
    long long n_tokens,
    float* __restrict__ out)
{
    __shared__ float4 xbuf[NSTAGE][TILE_PAIRS];   // 3 x 8 KB

    const int tix = threadIdx.x;
    const long long n_pairs = n_tokens >> 1;
    const long long P0 = (long long)blockIdx.x * (TILES_PER_BLOCK * TILE_PAIRS);

    const float4* x4 = reinterpret_cast<const float4*>(x);
    const int2*   t2 = reinterpret_cast<const int2*>(targets);

    float s0 = 0.0f, s1 = 0.0f;
    int   c1 = 0;

    const bool full_block = (P0 + TILES_PER_BLOCK * TILE_PAIRS) <= n_pairs;

    if (full_block) {
        // Prefetch first NSTAGE tiles (one commit group per tile).
        #pragma unroll
        for (int i = 0; i < NSTAGE; i++) {
            const float4* src = x4 + P0 + i * TILE_PAIRS + tix;
            cp_async16(&xbuf[i][tix],       src);
            cp_async16(&xbuf[i][256 + tix], src + 256);
            cp_async_commit();
        }

        int st = 0;
        #pragma unroll
        for (int i = 0; i < TILES_PER_BLOCK; i++) {
            const long long tb = P0 + (long long)i * TILE_PAIRS;

            // Targets for this tile: 2 coalesced LDG.64, independent of smem —
            // they overlap the cp.async wait below.
            const int2* tp = t2 + tb + tix;
            int2 b0 = tp[0];
            int2 b1 = tp[256];

            cp_async_wait<NSTAGE - 1>();   // this thread's tile-i copy done

            // Drain smem slots into registers (frees stage st for reuse by
            // THIS thread; no other thread ever touches these addresses).
            float4 a0 = xbuf[st][tix];
            float4 a1 = xbuf[st][256 + tix];

            // Refill stage st for tile i+NSTAGE before computing.
            if (i + NSTAGE < TILES_PER_BLOCK) {
                const float4* src = x4 + P0 + (long long)(i + NSTAGE) * TILE_PAIRS + tix;
                cp_async16(&xbuf[st][tix],       src);
                cp_async16(&xbuf[st][256 + tix], src + 256);
                cp_async_commit();
            }

            proc_pair(a0, b0, s0, s1, c1);
            proc_pair(a1, b1, s0, s1, c1);

            st = (st == NSTAGE - 1) ? 0 : st + 1;
        }
    } else {
        // Generic guarded path for the boundary block (rare / other shapes).
        for (long long p = P0 + tix; p < n_pairs &&
             p < P0 + TILES_PER_BLOCK * TILE_PAIRS; p += 256) {
            proc_pair(x4[p], t2[p], s0, s1, c1);
        }
    }

    // Odd trailing token.
    if ((n_tokens & 1) && blockIdx.x == 0 && tix == 0) {
        long long i = n_tokens - 1;
        float x0 = x[2 * i], x1v = x[2 * i + 1];
        int   t  = targets[i];
        float m   = fmaxf(x0, x1v);
        float d   = -fabsf(x0 - x1v);
        float lse = m + __logf(1.0f + __expf(d));
        if (t != 0) { s1 += x1v - lse; c1 += 1; }
        else        { s0 += x0 - lse; }
    }

    // warp reduction
    #pragma unroll
    for (int off = 16; off > 0; off >>= 1) {
        s0 += __shfl_down_sync(0xFFFFFFFFu, s0, off);
        s1 += __shfl_down_sync(0xFFFFFFFFu, s1, off);
        c1 += __shfl_down_sync(0xFFFFFFFFu, c1, off);
    }

    __shared__ float sh0[8];
    __shared__ float sh1[8];
    __shared__ int   shc[8];
    const int lane = tix & 31;
    const int wid  = tix >> 5;
    if (lane == 0) { sh0[wid] = s0; sh1[wid] = s1; shc[wid] = c1; }
    __syncthreads();

    __shared__ bool is_last;
    if (wid == 0) {
        s0 = (lane < 8) ? sh0[lane] : 0.0f;
        s1 = (lane < 8) ? sh1[lane] : 0.0f;
        c1 = (lane < 8) ? shc[lane] : 0;
        #pragma unroll
        for (int off = 4; off > 0; off >>= 1) {
            s0 += __shfl_down_sync(0xFFFFFFFFu, s0, off);
            s1 += __shfl_down_sync(0xFFFFFFFFu, s1, off);
            c1 += __shfl_down_sync(0xFFFFFFFFu, c1, off);
        }
        if (lane == 0) {
            atomicAdd(&g_sum0, (double)s0);
            atomicAdd(&g_sum1, (double)s1);
            atomicAdd(&g_cnt1, (unsigned long long)c1);
            __threadfence();
            unsigned int done = atomicAdd(&g_blocks_done, 1u);
            is_last = (done == gridDim.x - 1u);
        }
    }
    __syncthreads();

    if (is_last && tix == 0) {
        __threadfence();
        double sum0 = g_sum0;
        double sum1 = g_sum1;
        unsigned long long n1 = g_cnt1;
        unsigned long long n0 = (unsigned long long)n_tokens - n1;
        double r = (n1 > 0) ? (-sum1 / (double)n1) : 0.0;
        double p = (n0 > 0) ? (-sum0 / (double)n0) : 0.0;
        out[0] = (float)(p + r);
        g_sum0 = 0.0;
        g_sum1 = 0.0;
        g_cnt1 = 0ull;
        g_blocks_done = 0u;
    }
}

extern "C" void kernel_launch(void* const* d_in, const int* in_sizes, int n_in,
                              void* d_out, int out_size) {
    const float* x       = (const float*)d_in[0];
    const int*   targets = (const int*)d_in[1];
    float*       out     = (float*)d_out;

    const long long n_tokens = (long long)in_sizes[1];
    const long long n_pairs  = (n_tokens + 1) / 2;

    const int block = 256;
    const long long pairs_per_block = TILES_PER_BLOCK * TILE_PAIRS;  // 4096
    int grid = (int)((n_pairs + pairs_per_block - 1) / pairs_per_block);
    if (grid < 1) grid = 1;
    nll_pipe_kernel<<<grid, block>>>(x, targets, n_tokens, out);
}